// round 5
// baseline (speedup 1.0000x reference)
#include <cuda_runtime.h>
#include <math.h>

// Problem-shape capacities (fixed by the dataset): N=100000, E=800000,
// F_IN=96, H=128, C=64.
#define MAXN 100000
#define MAXE 800000
#define FIN 96
#define HID 128
#define COUT 64

// Scratch (static __device__ — no allocations allowed in kernel_launch).
// float4-typed so every vectorized reinterpret is 16B-aligned.
__device__ float4 g_dinv4[(MAXN + 3) / 4];               // deg -> d^{-1/2}
__device__ float4 g_h1_4[(size_t)MAXN * HID / 4];        // x@W1, then relu(agg1+b1)
__device__ float4 g_agg1_4[(size_t)MAXN * HID / 4];
__device__ float4 g_h2_4[(size_t)MAXN * COUT / 4];       // h@W2
__device__ float4 g_agg2_4[(size_t)MAXN * COUT / 4];
__device__ int    g_src[MAXE];                           // edge src as int32
__device__ int    g_dst[MAXE];                           // edge dst as int32
__device__ unsigned g_anyodd;                            // dtype-detect flag

#define g_dinv ((float*)g_dinv4)
#define g_h1   ((float*)g_h1_4)
#define g_agg1 ((float*)g_agg1_4)
#define g_h2   ((float*)g_h2_4)
#define g_agg2 ((float*)g_agg2_4)

// ---------------------------------------------------------------------------
// edge_index dtype detection + conversion to int32.
// If the buffer is int64 (little-endian, values in [0, 2^31)), every odd
// 32-bit word among the first 2E words is zero. If it is int32, the odd
// words are actual src node ids (random in [0,N)) and cannot all be zero.
// ---------------------------------------------------------------------------
__global__ void idx_reset_kernel() { g_anyodd = 0u; }

__global__ void idx_detect_kernel(const unsigned* __restrict__ w, int E) {
    unsigned acc = 0u;
    for (int i = blockIdx.x * blockDim.x + threadIdx.x; i < E;
         i += gridDim.x * blockDim.x)
        acc |= w[2 * i + 1];
    // warp-reduce then one atomic per warp
    for (int o = 16; o > 0; o >>= 1)
        acc |= __shfl_xor_sync(0xFFFFFFFFu, acc, o);
    if ((threadIdx.x & 31) == 0 && acc) atomicOr(&g_anyodd, acc);
}

__global__ void idx_convert_kernel(const void* __restrict__ ei, int E) {
    int e = blockIdx.x * blockDim.x + threadIdx.x;
    if (e >= E) return;
    if (g_anyodd) {          // int32 layout
        const int* p = (const int*)ei;
        g_src[e] = p[e];
        g_dst[e] = p[E + e];
    } else {                 // int64 layout
        const long long* p = (const long long*)ei;
        g_src[e] = (int)p[e];
        g_dst[e] = (int)p[E + e];
    }
}

// ---------------------------------------------------------------------------
// Degree / normalization
// ---------------------------------------------------------------------------
__global__ void deg_init_kernel(int N) {
    int i = blockIdx.x * blockDim.x + threadIdx.x;
    if (i < N) g_dinv[i] = 1.0f;   // self-loop contributes 1 to every degree
}

__global__ void deg_count_kernel(int E) {
    int e = blockIdx.x * blockDim.x + threadIdx.x;
    if (e < E) atomicAdd(&g_dinv[g_dst[e]], 1.0f);
}

__global__ void deg_finish_kernel(int N) {
    int i = blockIdx.x * blockDim.x + threadIdx.x;
    if (i < N) g_dinv[i] = rsqrtf(g_dinv[i]);
}

// ---------------------------------------------------------------------------
// GEMM1: g_h1[N,128] = x[N,96] @ W1[96,128]
// Block: 64 rows x 128 cols, 256 threads, 4x8 register tile, K split 48+48.
// ---------------------------------------------------------------------------
__global__ void gemm1_kernel(const float* __restrict__ x,
                             const float* __restrict__ W1, int N) {
    __shared__ __align__(16) float Xs[64][48];
    __shared__ __align__(16) float Ws[48][128];
    const int tid = threadIdx.x;
    const int ty = tid >> 4;          // 0..15 -> rows ty*4..ty*4+3
    const int tx = tid & 15;          // 0..15 -> cols tx*8..tx*8+7
    const int rowBase = blockIdx.x * 64;

    float acc[4][8];
#pragma unroll
    for (int i = 0; i < 4; i++)
#pragma unroll
        for (int j = 0; j < 8; j++) acc[i][j] = 0.0f;

    for (int k0 = 0; k0 < FIN; k0 += 48) {
        // Load X tile: 64x48 floats = 768 float4
#pragma unroll
        for (int t = tid; t < 768; t += 256) {
            int r = t / 12, c = (t % 12) * 4;
            int gr = rowBase + r;
            float4 v = make_float4(0.f, 0.f, 0.f, 0.f);
            if (gr < N)
                v = *(const float4*)(x + (size_t)gr * FIN + k0 + c);
            *(float4*)&Xs[r][c] = v;
        }
        // Load W tile: 48x128 floats = 1536 float4
#pragma unroll
        for (int t = tid; t < 1536; t += 256) {
            int r = t >> 5, c = (t & 31) * 4;
            *(float4*)&Ws[r][c] = *(const float4*)(W1 + (size_t)(k0 + r) * HID + c);
        }
        __syncthreads();

#pragma unroll 4
        for (int k = 0; k < 48; k++) {
            float a[4];
#pragma unroll
            for (int i = 0; i < 4; i++) a[i] = Xs[ty * 4 + i][k];
            float b[8];
            *(float4*)&b[0] = *(float4*)&Ws[k][tx * 8];
            *(float4*)&b[4] = *(float4*)&Ws[k][tx * 8 + 4];
#pragma unroll
            for (int i = 0; i < 4; i++)
#pragma unroll
                for (int j = 0; j < 8; j++) acc[i][j] = fmaf(a[i], b[j], acc[i][j]);
        }
        __syncthreads();
    }

#pragma unroll
    for (int i = 0; i < 4; i++) {
        int gr = rowBase + ty * 4 + i;
        if (gr < N) {
            float4 o0 = make_float4(acc[i][0], acc[i][1], acc[i][2], acc[i][3]);
            float4 o1 = make_float4(acc[i][4], acc[i][5], acc[i][6], acc[i][7]);
            *(float4*)(g_h1 + (size_t)gr * HID + tx * 8) = o0;
            *(float4*)(g_h1 + (size_t)gr * HID + tx * 8 + 4) = o1;
        }
    }
}

// ---------------------------------------------------------------------------
// GEMM2: g_h2[N,64] = g_h1[N,128] @ W2[128,64]
// Block: 64 rows x 64 cols, 256 threads, 4x4 register tile, K split 64+64.
// ---------------------------------------------------------------------------
__global__ void gemm2_kernel(const float* __restrict__ W2, int N) {
    __shared__ __align__(16) float Xs[64][64];
    __shared__ __align__(16) float Ws[64][64];
    const int tid = threadIdx.x;
    const int ty = tid >> 4;
    const int tx = tid & 15;
    const int rowBase = blockIdx.x * 64;

    float acc[4][4];
#pragma unroll
    for (int i = 0; i < 4; i++)
#pragma unroll
        for (int j = 0; j < 4; j++) acc[i][j] = 0.0f;

    for (int k0 = 0; k0 < HID; k0 += 64) {
        // X tile: 64x64 = 1024 float4
#pragma unroll
        for (int t = tid; t < 1024; t += 256) {
            int r = t >> 4, c = (t & 15) * 4;
            int gr = rowBase + r;
            float4 v = make_float4(0.f, 0.f, 0.f, 0.f);
            if (gr < N)
                v = *(const float4*)(g_h1 + (size_t)gr * HID + k0 + c);
            *(float4*)&Xs[r][c] = v;
        }
        // W tile: 64x64 = 1024 float4
#pragma unroll
        for (int t = tid; t < 1024; t += 256) {
            int r = t >> 4, c = (t & 15) * 4;
            *(float4*)&Ws[r][c] = *(const float4*)(W2 + (size_t)(k0 + r) * COUT + c);
        }
        __syncthreads();

#pragma unroll 4
        for (int k = 0; k < 64; k++) {
            float a[4];
#pragma unroll
            for (int i = 0; i < 4; i++) a[i] = Xs[ty * 4 + i][k];
            float4 b = *(float4*)&Ws[k][tx * 4];
#pragma unroll
            for (int i = 0; i < 4; i++) {
                acc[i][0] = fmaf(a[i], b.x, acc[i][0]);
                acc[i][1] = fmaf(a[i], b.y, acc[i][1]);
                acc[i][2] = fmaf(a[i], b.z, acc[i][2]);
                acc[i][3] = fmaf(a[i], b.w, acc[i][3]);
            }
        }
        __syncthreads();
    }

#pragma unroll
    for (int i = 0; i < 4; i++) {
        int gr = rowBase + ty * 4 + i;
        if (gr < N) {
            float4 o = make_float4(acc[i][0], acc[i][1], acc[i][2], acc[i][3]);
            *(float4*)(g_h2 + (size_t)gr * COUT + tx * 4) = o;
        }
    }
}

// ---------------------------------------------------------------------------
// Self-loop init: agg[i] = h[i] * dinv[i]^2   (float4-vectorized)
// ---------------------------------------------------------------------------
__global__ void selfloop1_kernel(int N) {
    int idx = blockIdx.x * blockDim.x + threadIdx.x;   // over N*32 float4
    if (idx >= N * 32) return;
    int i = idx >> 5;
    float di = g_dinv[i];
    float w = di * di;
    float4 v = g_h1_4[idx];
    v.x *= w; v.y *= w; v.z *= w; v.w *= w;
    g_agg1_4[idx] = v;
}

__global__ void selfloop2_kernel(int N) {
    int idx = blockIdx.x * blockDim.x + threadIdx.x;   // over N*16 float4
    if (idx >= N * 16) return;
    int i = idx >> 4;
    float di = g_dinv[i];
    float w = di * di;
    float4 v = g_h2_4[idx];
    v.x *= w; v.y *= w; v.z *= w; v.w *= w;
    g_agg2_4[idx] = v;
}

// ---------------------------------------------------------------------------
// Edge aggregation layer 1: one warp per edge, 128 floats.
// agg1[dst] += h1[src] * dinv[src]*dinv[dst]
// ---------------------------------------------------------------------------
__global__ void edge_agg1_kernel(int E) {
    int gid = blockIdx.x * blockDim.x + threadIdx.x;
    int e = gid >> 5;
    int lane = gid & 31;
    if (e >= E) return;
    int s = g_src[e];
    int d = g_dst[e];
    float w = g_dinv[s] * g_dinv[d];
    float4 v = g_h1_4[(size_t)s * 32 + lane];
    float* o = g_agg1 + (size_t)d * HID + lane * 4;
    atomicAdd(o + 0, v.x * w);
    atomicAdd(o + 1, v.y * w);
    atomicAdd(o + 2, v.z * w);
    atomicAdd(o + 3, v.w * w);
}

// Edge aggregation layer 2: 16 threads per edge, 64 floats.
__global__ void edge_agg2_kernel(int E) {
    int gid = blockIdx.x * blockDim.x + threadIdx.x;
    int e = gid >> 4;
    int l = gid & 15;
    if (e >= E) return;
    int s = g_src[e];
    int d = g_dst[e];
    float w = g_dinv[s] * g_dinv[d];
    float4 v = g_h2_4[(size_t)s * 16 + l];
    float* o = g_agg2 + (size_t)d * COUT + l * 4;
    atomicAdd(o + 0, v.x * w);
    atomicAdd(o + 1, v.y * w);
    atomicAdd(o + 2, v.z * w);
    atomicAdd(o + 3, v.w * w);
}

// ---------------------------------------------------------------------------
// h = relu(agg1 + b1); write embedding to output; store h back into g_h1.
// ---------------------------------------------------------------------------
__global__ void bias_relu_embed_kernel(const float* __restrict__ b1,
                                       float* __restrict__ emb, int N) {
    int idx = blockIdx.x * blockDim.x + threadIdx.x;   // over N*32 float4
    if (idx >= N * 32) return;
    int c4 = idx & 31;
    float4 v = g_agg1_4[idx];
    float4 b = *(const float4*)(b1 + c4 * 4);
    v.x = fmaxf(v.x + b.x, 0.0f);
    v.y = fmaxf(v.y + b.y, 0.0f);
    v.z = fmaxf(v.z + b.z, 0.0f);
    v.w = fmaxf(v.w + b.w, 0.0f);
    g_h1_4[idx] = v;
    if (emb) ((float4*)emb)[idx] = v;
}

// ---------------------------------------------------------------------------
// log_softmax over 64 columns: one warp per row (2 values per lane).
// out = (agg2 + b2) - max - log(sum exp(.-max))
// ---------------------------------------------------------------------------
__global__ void logsoftmax_kernel(const float* __restrict__ b2,
                                  float* __restrict__ out, int N) {
    int gid = blockIdx.x * blockDim.x + threadIdx.x;
    int row = gid >> 5;
    int lane = gid & 31;
    if (row >= N) return;
    float2 v = *(const float2*)(g_agg2 + (size_t)row * COUT + lane * 2);
    float2 bb = *(const float2*)(b2 + lane * 2);
    v.x += bb.x;
    v.y += bb.y;
    float m = fmaxf(v.x, v.y);
#pragma unroll
    for (int o = 16; o > 0; o >>= 1)
        m = fmaxf(m, __shfl_xor_sync(0xFFFFFFFFu, m, o));
    float s = expf(v.x - m) + expf(v.y - m);
#pragma unroll
    for (int o = 16; o > 0; o >>= 1)
        s += __shfl_xor_sync(0xFFFFFFFFu, s, o);
    float l = logf(s) + m;
    float2 r;
    r.x = v.x - l;
    r.y = v.y - l;
    *(float2*)(out + (size_t)row * COUT + lane * 2) = r;
}

// ---------------------------------------------------------------------------
extern "C" void kernel_launch(void* const* d_in, const int* in_sizes, int n_in,
                              void* d_out, int out_size) {
    const float* x  = (const float*)d_in[0];
    const float* W1 = (const float*)d_in[1];
    const float* b1 = (const float*)d_in[2];
    const float* W2 = (const float*)d_in[3];
    const float* b2 = (const float*)d_in[4];
    const void*  ei = d_in[5];

    const int H   = in_sizes[2];                 // 128
    const int Fin = in_sizes[1] / H;             // 96
    const int C   = in_sizes[4];                 // 64
    const int N   = in_sizes[0] / Fin;           // 100000
    const int E   = in_sizes[5] / 2;             // 800000

    float* out = (float*)d_out;
    // Output layout follows the reference return order: log_softmax [N,C]
    // then embedding [N,H] (only if the harness asked for both).
    float* emb = ((long long)out_size >= (long long)N * (C + H))
                     ? out + (size_t)N * C
                     : nullptr;

    const int T = 256;

    // Edge-index dtype detect + convert to int32
    idx_reset_kernel<<<1, 1>>>();
    idx_detect_kernel<<<256, 256>>>((const unsigned*)ei, E);
    idx_convert_kernel<<<(E + T - 1) / T, T>>>(ei, E);

    // Normalization
    deg_init_kernel<<<(N + T - 1) / T, T>>>(N);
    deg_count_kernel<<<(E + T - 1) / T, T>>>(E);
    deg_finish_kernel<<<(N + T - 1) / T, T>>>(N);

    // Layer 1
    gemm1_kernel<<<(N + 63) / 64, 256>>>(x, W1, N);
    selfloop1_kernel<<<(N * 32 + T - 1) / T, T>>>(N);
    edge_agg1_kernel<<<(int)(((long long)E * 32 + T - 1) / T), T>>>(E);
    bias_relu_embed_kernel<<<(N * 32 + T - 1) / T, T>>>(b1, emb, N);

    // Layer 2
    gemm2_kernel<<<(N + 63) / 64, 256>>>(W2, N);
    selfloop2_kernel<<<(N * 16 + T - 1) / T, T>>>(N);
    edge_agg2_kernel<<<(int)(((long long)E * 16 + T - 1) / T), T>>>(E);

    // Output head
    logsoftmax_kernel<<<(int)(((long long)N * 32 + T - 1) / T), T>>>(b2, out, N);
}

// round 6
// speedup vs baseline: 1.4134x; 1.4134x over previous
#include <cuda_runtime.h>
#include <math.h>

// Problem-shape capacities (fixed by the dataset): N=100000, E=800000,
// F_IN=96, H=128, C=64.
#define MAXN 100000
#define MAXE 800000
#define FIN 96
#define HID 128
#define COUT 64

// Scratch (static __device__ — no allocations allowed in kernel_launch).
// float4-typed so every vectorized reinterpret is 16B-aligned.
__device__ float4 g_dinv4[(MAXN + 3) / 4];               // deg -> d^{-1/2}
__device__ float4 g_h1_4[(size_t)MAXN * HID / 4];        // x@W1, then relu(agg1+b1)
__device__ float4 g_agg1_4[(size_t)MAXN * HID / 4];
__device__ float4 g_h2_4[(size_t)MAXN * COUT / 4];       // h@W2
__device__ float4 g_agg2_4[(size_t)MAXN * COUT / 4];
__device__ int    g_src[MAXE];                           // edge src as int32
__device__ int    g_dst[MAXE];                           // edge dst as int32
__device__ float  g_norm[MAXE];                          // dinv[src]*dinv[dst]
__device__ unsigned g_anyodd;                            // dtype-detect flag

#define g_dinv ((float*)g_dinv4)
#define g_h1   ((float*)g_h1_4)
#define g_agg1 ((float*)g_agg1_4)
#define g_h2   ((float*)g_h2_4)
#define g_agg2 ((float*)g_agg2_4)

// 128-bit no-return global reduction (sm_90+): one RED instead of 4 atomicAdds.
__device__ __forceinline__ void red_add_v4(float* p, float a, float b,
                                           float c, float d) {
    asm volatile("red.global.add.v4.f32 [%0], {%1, %2, %3, %4};"
                 :: "l"(p), "f"(a), "f"(b), "f"(c), "f"(d)
                 : "memory");
}

// ---------------------------------------------------------------------------
// edge_index dtype detection + conversion to int32.
// int64 (LE, values < 2^31): every odd 32-bit word of the first 2E words is 0.
// int32: odd words are real src node ids and cannot all be zero.
// ---------------------------------------------------------------------------
__global__ void idx_reset_kernel() { g_anyodd = 0u; }

__global__ void idx_detect_kernel(const unsigned* __restrict__ w, int E) {
    unsigned acc = 0u;
    for (int i = blockIdx.x * blockDim.x + threadIdx.x; i < E;
         i += gridDim.x * blockDim.x)
        acc |= w[2 * i + 1];
    for (int o = 16; o > 0; o >>= 1)
        acc |= __shfl_xor_sync(0xFFFFFFFFu, acc, o);
    if ((threadIdx.x & 31) == 0 && acc) atomicOr(&g_anyodd, acc);
}

__global__ void idx_convert_kernel(const void* __restrict__ ei, int E) {
    int e = blockIdx.x * blockDim.x + threadIdx.x;
    if (e >= E) return;
    if (g_anyodd) {          // int32 layout
        const int* p = (const int*)ei;
        g_src[e] = p[e];
        g_dst[e] = p[E + e];
    } else {                 // int64 layout
        const long long* p = (const long long*)ei;
        g_src[e] = (int)p[e];
        g_dst[e] = (int)p[E + e];
    }
}

// ---------------------------------------------------------------------------
// Degree / normalization
// ---------------------------------------------------------------------------
__global__ void deg_init_kernel(int N) {
    int i = blockIdx.x * blockDim.x + threadIdx.x;
    if (i < N) g_dinv[i] = 1.0f;   // self-loop contributes 1 to every degree
}

__global__ void deg_count_kernel(int E) {
    int e = blockIdx.x * blockDim.x + threadIdx.x;
    if (e < E) atomicAdd(&g_dinv[g_dst[e]], 1.0f);
}

__global__ void deg_finish_kernel(int N) {
    int i = blockIdx.x * blockDim.x + threadIdx.x;
    if (i < N) g_dinv[i] = rsqrtf(g_dinv[i]);
}

// Per-edge norm = dinv[src] * dinv[dst]  (one load per lane in hot kernels)
__global__ void norm_kernel(int E) {
    int e = blockIdx.x * blockDim.x + threadIdx.x;
    if (e < E) g_norm[e] = g_dinv[g_src[e]] * g_dinv[g_dst[e]];
}

// ---------------------------------------------------------------------------
// GEMM1: g_h1[N,128] = x[N,96] @ W1[96,128]; also g_agg1 = h1 * dinv^2
// Block: 64 rows x 128 cols, 256 threads, 4x8 register tile, K split 48+48.
// ---------------------------------------------------------------------------
__global__ void gemm1_kernel(const float* __restrict__ x,
                             const float* __restrict__ W1, int N) {
    __shared__ __align__(16) float Xs[64][48];
    __shared__ __align__(16) float Ws[48][128];
    const int tid = threadIdx.x;
    const int ty = tid >> 4;          // 0..15 -> rows ty*4..ty*4+3
    const int tx = tid & 15;          // 0..15 -> cols tx*8..tx*8+7
    const int rowBase = blockIdx.x * 64;

    float acc[4][8];
#pragma unroll
    for (int i = 0; i < 4; i++)
#pragma unroll
        for (int j = 0; j < 8; j++) acc[i][j] = 0.0f;

    for (int k0 = 0; k0 < FIN; k0 += 48) {
#pragma unroll
        for (int t = tid; t < 768; t += 256) {
            int r = t / 12, c = (t % 12) * 4;
            int gr = rowBase + r;
            float4 v = make_float4(0.f, 0.f, 0.f, 0.f);
            if (gr < N)
                v = *(const float4*)(x + (size_t)gr * FIN + k0 + c);
            *(float4*)&Xs[r][c] = v;
        }
#pragma unroll
        for (int t = tid; t < 1536; t += 256) {
            int r = t >> 5, c = (t & 31) * 4;
            *(float4*)&Ws[r][c] = *(const float4*)(W1 + (size_t)(k0 + r) * HID + c);
        }
        __syncthreads();

#pragma unroll 4
        for (int k = 0; k < 48; k++) {
            float a[4];
#pragma unroll
            for (int i = 0; i < 4; i++) a[i] = Xs[ty * 4 + i][k];
            float b[8];
            *(float4*)&b[0] = *(float4*)&Ws[k][tx * 8];
            *(float4*)&b[4] = *(float4*)&Ws[k][tx * 8 + 4];
#pragma unroll
            for (int i = 0; i < 4; i++)
#pragma unroll
                for (int j = 0; j < 8; j++) acc[i][j] = fmaf(a[i], b[j], acc[i][j]);
        }
        __syncthreads();
    }

#pragma unroll
    for (int i = 0; i < 4; i++) {
        int gr = rowBase + ty * 4 + i;
        if (gr < N) {
            float di = g_dinv[gr];
            float w = di * di;
            float4 o0 = make_float4(acc[i][0], acc[i][1], acc[i][2], acc[i][3]);
            float4 o1 = make_float4(acc[i][4], acc[i][5], acc[i][6], acc[i][7]);
            *(float4*)(g_h1 + (size_t)gr * HID + tx * 8) = o0;
            *(float4*)(g_h1 + (size_t)gr * HID + tx * 8 + 4) = o1;
            float4 s0 = make_float4(o0.x * w, o0.y * w, o0.z * w, o0.w * w);
            float4 s1 = make_float4(o1.x * w, o1.y * w, o1.z * w, o1.w * w);
            *(float4*)(g_agg1 + (size_t)gr * HID + tx * 8) = s0;
            *(float4*)(g_agg1 + (size_t)gr * HID + tx * 8 + 4) = s1;
        }
    }
}

// ---------------------------------------------------------------------------
// GEMM2: g_h2[N,64] = g_h1[N,128] @ W2[128,64]; also g_agg2 = h2 * dinv^2
// Block: 64 rows x 64 cols, 256 threads, 4x4 register tile, K split 64+64.
// ---------------------------------------------------------------------------
__global__ void gemm2_kernel(const float* __restrict__ W2, int N) {
    __shared__ __align__(16) float Xs[64][64];
    __shared__ __align__(16) float Ws[64][64];
    const int tid = threadIdx.x;
    const int ty = tid >> 4;
    const int tx = tid & 15;
    const int rowBase = blockIdx.x * 64;

    float acc[4][4];
#pragma unroll
    for (int i = 0; i < 4; i++)
#pragma unroll
        for (int j = 0; j < 4; j++) acc[i][j] = 0.0f;

    for (int k0 = 0; k0 < HID; k0 += 64) {
#pragma unroll
        for (int t = tid; t < 1024; t += 256) {
            int r = t >> 4, c = (t & 15) * 4;
            int gr = rowBase + r;
            float4 v = make_float4(0.f, 0.f, 0.f, 0.f);
            if (gr < N)
                v = *(const float4*)(g_h1 + (size_t)gr * HID + k0 + c);
            *(float4*)&Xs[r][c] = v;
        }
#pragma unroll
        for (int t = tid; t < 1024; t += 256) {
            int r = t >> 4, c = (t & 15) * 4;
            *(float4*)&Ws[r][c] = *(const float4*)(W2 + (size_t)(k0 + r) * COUT + c);
        }
        __syncthreads();

#pragma unroll 4
        for (int k = 0; k < 64; k++) {
            float a[4];
#pragma unroll
            for (int i = 0; i < 4; i++) a[i] = Xs[ty * 4 + i][k];
            float4 b = *(float4*)&Ws[k][tx * 4];
#pragma unroll
            for (int i = 0; i < 4; i++) {
                acc[i][0] = fmaf(a[i], b.x, acc[i][0]);
                acc[i][1] = fmaf(a[i], b.y, acc[i][1]);
                acc[i][2] = fmaf(a[i], b.z, acc[i][2]);
                acc[i][3] = fmaf(a[i], b.w, acc[i][3]);
            }
        }
        __syncthreads();
    }

#pragma unroll
    for (int i = 0; i < 4; i++) {
        int gr = rowBase + ty * 4 + i;
        if (gr < N) {
            float di = g_dinv[gr];
            float w = di * di;
            float4 o = make_float4(acc[i][0], acc[i][1], acc[i][2], acc[i][3]);
            *(float4*)(g_h2 + (size_t)gr * COUT + tx * 4) = o;
            float4 s = make_float4(o.x * w, o.y * w, o.z * w, o.w * w);
            *(float4*)(g_agg2 + (size_t)gr * COUT + tx * 4) = s;
        }
    }
}

// ---------------------------------------------------------------------------
// Edge aggregation layer 1: one warp per edge, 128 floats, vector RED.
// agg1[dst] += h1[src] * norm[e]
// ---------------------------------------------------------------------------
__global__ void edge_agg1_kernel(int E) {
    int gid = blockIdx.x * blockDim.x + threadIdx.x;
    int e = gid >> 5;
    int lane = gid & 31;
    if (e >= E) return;
    int s = g_src[e];
    int d = g_dst[e];
    float w = g_norm[e];
    float4 v = g_h1_4[(size_t)s * 32 + lane];
    red_add_v4(g_agg1 + (size_t)d * HID + lane * 4,
               v.x * w, v.y * w, v.z * w, v.w * w);
}

// Edge aggregation layer 2: 16 threads per edge, 64 floats, vector RED.
__global__ void edge_agg2_kernel(int E) {
    int gid = blockIdx.x * blockDim.x + threadIdx.x;
    int e = gid >> 4;
    int l = gid & 15;
    if (e >= E) return;
    int s = g_src[e];
    int d = g_dst[e];
    float w = g_norm[e];
    float4 v = g_h2_4[(size_t)s * 16 + l];
    red_add_v4(g_agg2 + (size_t)d * COUT + l * 4,
               v.x * w, v.y * w, v.z * w, v.w * w);
}

// ---------------------------------------------------------------------------
// h = relu(agg1 + b1); write embedding to output; store h back into g_h1.
// ---------------------------------------------------------------------------
__global__ void bias_relu_embed_kernel(const float* __restrict__ b1,
                                       float* __restrict__ emb, int N) {
    int idx = blockIdx.x * blockDim.x + threadIdx.x;   // over N*32 float4
    if (idx >= N * 32) return;
    int c4 = idx & 31;
    float4 v = g_agg1_4[idx];
    float4 b = *(const float4*)(b1 + c4 * 4);
    v.x = fmaxf(v.x + b.x, 0.0f);
    v.y = fmaxf(v.y + b.y, 0.0f);
    v.z = fmaxf(v.z + b.z, 0.0f);
    v.w = fmaxf(v.w + b.w, 0.0f);
    g_h1_4[idx] = v;
    if (emb) ((float4*)emb)[idx] = v;
}

// ---------------------------------------------------------------------------
// log_softmax over 64 columns: one warp per row (2 values per lane).
// ---------------------------------------------------------------------------
__global__ void logsoftmax_kernel(const float* __restrict__ b2,
                                  float* __restrict__ out, int N) {
    int gid = blockIdx.x * blockDim.x + threadIdx.x;
    int row = gid >> 5;
    int lane = gid & 31;
    if (row >= N) return;
    float2 v = *(const float2*)(g_agg2 + (size_t)row * COUT + lane * 2);
    float2 bb = *(const float2*)(b2 + lane * 2);
    v.x += bb.x;
    v.y += bb.y;
    float m = fmaxf(v.x, v.y);
#pragma unroll
    for (int o = 16; o > 0; o >>= 1)
        m = fmaxf(m, __shfl_xor_sync(0xFFFFFFFFu, m, o));
    float s = expf(v.x - m) + expf(v.y - m);
#pragma unroll
    for (int o = 16; o > 0; o >>= 1)
        s += __shfl_xor_sync(0xFFFFFFFFu, s, o);
    float l = logf(s) + m;
    float2 r;
    r.x = v.x - l;
    r.y = v.y - l;
    *(float2*)(out + (size_t)row * COUT + lane * 2) = r;
}

// ---------------------------------------------------------------------------
extern "C" void kernel_launch(void* const* d_in, const int* in_sizes, int n_in,
                              void* d_out, int out_size) {
    const float* x  = (const float*)d_in[0];
    const float* W1 = (const float*)d_in[1];
    const float* b1 = (const float*)d_in[2];
    const float* W2 = (const float*)d_in[3];
    const float* b2 = (const float*)d_in[4];
    const void*  ei = d_in[5];

    const int H   = in_sizes[2];                 // 128
    const int Fin = in_sizes[1] / H;             // 96
    const int C   = in_sizes[4];                 // 64
    const int N   = in_sizes[0] / Fin;           // 100000
    const int E   = in_sizes[5] / 2;             // 800000

    float* out = (float*)d_out;
    // Output layout follows the reference return order: log_softmax [N,C]
    // then embedding [N,H] (only if the harness asked for both).
    float* emb = ((long long)out_size >= (long long)N * (C + H))
                     ? out + (size_t)N * C
                     : nullptr;

    const int T = 256;

    // Edge-index dtype detect + convert to int32
    idx_reset_kernel<<<1, 1>>>();
    idx_detect_kernel<<<256, 256>>>((const unsigned*)ei, E);
    idx_convert_kernel<<<(E + T - 1) / T, T>>>(ei, E);

    // Normalization
    deg_init_kernel<<<(N + T - 1) / T, T>>>(N);
    deg_count_kernel<<<(E + T - 1) / T, T>>>(E);
    deg_finish_kernel<<<(N + T - 1) / T, T>>>(N);
    norm_kernel<<<(E + T - 1) / T, T>>>(E);

    // Layer 1 (self-loop term fused into GEMM1 epilogue)
    gemm1_kernel<<<(N + 63) / 64, 256>>>(x, W1, N);
    edge_agg1_kernel<<<(int)(((long long)E * 32 + T - 1) / T), T>>>(E);
    bias_relu_embed_kernel<<<(N * 32 + T - 1) / T, T>>>(b1, emb, N);

    // Layer 2 (self-loop term fused into GEMM2 epilogue)
    gemm2_kernel<<<(N + 63) / 64, 256>>>(W2, N);
    edge_agg2_kernel<<<(int)(((long long)E * 16 + T - 1) / T), T>>>(E);

    // Output head
    logsoftmax_kernel<<<(int)(((long long)N * 32 + T - 1) / T), T>>>(b2, out, N);
}

// round 7
// speedup vs baseline: 1.7176x; 1.2152x over previous
#include <cuda_runtime.h>
#include <math.h>

// Problem shape (fixed by the dataset): N=100000, E=800000, F_IN=96, H=128, C=64.
#define MAXN 100000
#define MAXE 800000
#define FIN 96
#define HID 128
#define COUT 64
#define NBLK ((MAXN + 255) / 256)

// Scratch (static __device__ — no allocations allowed in kernel_launch).
__device__ float4 g_dinv4[(MAXN + 3) / 4];            // d^{-1/2}
__device__ float4 g_h1_4[(size_t)MAXN * HID / 4];     // x@W1
__device__ float4 g_h1b_4[(size_t)MAXN * HID / 4];    // relu(agg1+b1)
__device__ float4 g_h2_4[(size_t)MAXN * COUT / 4];    // h1b@W2
__device__ int    g_src[MAXE];                        // edge src as int32
__device__ int    g_dst[MAXE];                        // edge dst as int32
__device__ int    g_cnt[MAXN];                        // in-degree (no self loop)
__device__ int    g_off[MAXN];                        // CSR row offsets (excl scan)
__device__ int    g_cur[MAXN];                        // scatter cursors
__device__ int    g_bsum[NBLK];                       // scan block sums
__device__ int    g_bbase[NBLK];                      // scanned block bases
__device__ int    g_eidx[MAXE];                       // CSR: src per slot
__device__ float  g_ew[MAXE];                         // CSR: dinv[src] per slot
__device__ unsigned g_anyodd;                         // dtype-detect flag

#define g_dinv ((float*)g_dinv4)
#define g_h1   ((float*)g_h1_4)
#define g_h1b  ((float*)g_h1b_4)
#define g_h2   ((float*)g_h2_4)

// ---------------------------------------------------------------------------
// edge_index dtype detection + conversion to int32.
// int64 (LE, ids < 2^31): every odd 32-bit word of the first 2E words is 0.
// int32: odd words are real src node ids and cannot all be zero.
// ---------------------------------------------------------------------------
__global__ void idx_reset_kernel() { g_anyodd = 0u; }

__global__ void idx_detect_kernel(const unsigned* __restrict__ w, int E) {
    unsigned acc = 0u;
    for (int i = blockIdx.x * blockDim.x + threadIdx.x; i < E;
         i += gridDim.x * blockDim.x)
        acc |= w[2 * i + 1];
    for (int o = 16; o > 0; o >>= 1)
        acc |= __shfl_xor_sync(0xFFFFFFFFu, acc, o);
    if ((threadIdx.x & 31) == 0 && acc) atomicOr(&g_anyodd, acc);
}

// Convert indices AND count in-degrees in the same pass.
__global__ void idx_convert_count_kernel(const void* __restrict__ ei, int E) {
    int e = blockIdx.x * blockDim.x + threadIdx.x;
    if (e >= E) return;
    int s, d;
    if (g_anyodd) {          // int32 layout
        const int* p = (const int*)ei;
        s = p[e]; d = p[E + e];
    } else {                 // int64 layout
        const long long* p = (const long long*)ei;
        s = (int)p[e]; d = (int)p[E + e];
    }
    g_src[e] = s;
    g_dst[e] = d;
    atomicAdd(&g_cnt[d], 1);
}

__global__ void cnt_zero_kernel(int N) {
    int i = blockIdx.x * blockDim.x + threadIdx.x;
    if (i < N) g_cnt[i] = 0;
}

// ---------------------------------------------------------------------------
// Exclusive scan of g_cnt into g_off (3 stages).
// ---------------------------------------------------------------------------
__global__ void scanA_kernel(int N) {          // per-block inclusive scan
    __shared__ int sm[256];
    int i = blockIdx.x * 256 + threadIdx.x;
    int v = (i < N) ? g_cnt[i] : 0;
    sm[threadIdx.x] = v;
    __syncthreads();
#pragma unroll
    for (int o = 1; o < 256; o <<= 1) {
        int t = (threadIdx.x >= o) ? sm[threadIdx.x - o] : 0;
        __syncthreads();
        sm[threadIdx.x] += t;
        __syncthreads();
    }
    if (i < N) g_off[i] = sm[threadIdx.x] - v;     // exclusive within block
    if (threadIdx.x == 255) g_bsum[blockIdx.x] = sm[255];
}

__global__ void scanB_kernel(int nblk) {       // scan block sums (1 block, 512 thr)
    __shared__ int sm[512];
    int i = threadIdx.x;
    int v = (i < nblk) ? g_bsum[i] : 0;
    sm[i] = v;
    __syncthreads();
#pragma unroll
    for (int o = 1; o < 512; o <<= 1) {
        int t = (i >= o) ? sm[i - o] : 0;
        __syncthreads();
        sm[i] += t;
        __syncthreads();
    }
    if (i < nblk) g_bbase[i] = sm[i] - v;          // exclusive
}

__global__ void scanC_kernel(int N) {          // add bases; init dinv + cursors
    int i = blockIdx.x * blockDim.x + threadIdx.x;
    if (i >= N) return;
    g_off[i] += g_bbase[i >> 8];
    g_cur[i] = 0;
    g_dinv[i] = rsqrtf((float)(g_cnt[i] + 1));     // +1 = self loop
}

// Scatter edges into CSR slots; store dinv[src] as the edge weight.
__global__ void scatter_kernel(int E) {
    int e = blockIdx.x * blockDim.x + threadIdx.x;
    if (e >= E) return;
    int s = g_src[e], d = g_dst[e];
    int pos = g_off[d] + atomicAdd(&g_cur[d], 1);
    g_eidx[pos] = s;
    g_ew[pos] = g_dinv[s];
}

// ---------------------------------------------------------------------------
// GEMM1: g_h1[N,128] = x[N,96] @ W1[96,128]
// ---------------------------------------------------------------------------
__global__ void gemm1_kernel(const float* __restrict__ x,
                             const float* __restrict__ W1, int N) {
    __shared__ __align__(16) float Xs[64][48];
    __shared__ __align__(16) float Ws[48][128];
    const int tid = threadIdx.x;
    const int ty = tid >> 4;
    const int tx = tid & 15;
    const int rowBase = blockIdx.x * 64;

    float acc[4][8];
#pragma unroll
    for (int i = 0; i < 4; i++)
#pragma unroll
        for (int j = 0; j < 8; j++) acc[i][j] = 0.0f;

    for (int k0 = 0; k0 < FIN; k0 += 48) {
#pragma unroll
        for (int t = tid; t < 768; t += 256) {
            int r = t / 12, c = (t % 12) * 4;
            int gr = rowBase + r;
            float4 v = make_float4(0.f, 0.f, 0.f, 0.f);
            if (gr < N)
                v = *(const float4*)(x + (size_t)gr * FIN + k0 + c);
            *(float4*)&Xs[r][c] = v;
        }
#pragma unroll
        for (int t = tid; t < 1536; t += 256) {
            int r = t >> 5, c = (t & 31) * 4;
            *(float4*)&Ws[r][c] = *(const float4*)(W1 + (size_t)(k0 + r) * HID + c);
        }
        __syncthreads();

#pragma unroll 4
        for (int k = 0; k < 48; k++) {
            float a[4];
#pragma unroll
            for (int i = 0; i < 4; i++) a[i] = Xs[ty * 4 + i][k];
            float b[8];
            *(float4*)&b[0] = *(float4*)&Ws[k][tx * 8];
            *(float4*)&b[4] = *(float4*)&Ws[k][tx * 8 + 4];
#pragma unroll
            for (int i = 0; i < 4; i++)
#pragma unroll
                for (int j = 0; j < 8; j++) acc[i][j] = fmaf(a[i], b[j], acc[i][j]);
        }
        __syncthreads();
    }

#pragma unroll
    for (int i = 0; i < 4; i++) {
        int gr = rowBase + ty * 4 + i;
        if (gr < N) {
            float4 o0 = make_float4(acc[i][0], acc[i][1], acc[i][2], acc[i][3]);
            float4 o1 = make_float4(acc[i][4], acc[i][5], acc[i][6], acc[i][7]);
            *(float4*)(g_h1 + (size_t)gr * HID + tx * 8) = o0;
            *(float4*)(g_h1 + (size_t)gr * HID + tx * 8 + 4) = o1;
        }
    }
}

// ---------------------------------------------------------------------------
// GEMM2: g_h2[N,64] = g_h1b[N,128] @ W2[128,64]
// ---------------------------------------------------------------------------
__global__ void gemm2_kernel(const float* __restrict__ W2, int N) {
    __shared__ __align__(16) float Xs[64][64];
    __shared__ __align__(16) float Ws[64][64];
    const int tid = threadIdx.x;
    const int ty = tid >> 4;
    const int tx = tid & 15;
    const int rowBase = blockIdx.x * 64;

    float acc[4][4];
#pragma unroll
    for (int i = 0; i < 4; i++)
#pragma unroll
        for (int j = 0; j < 4; j++) acc[i][j] = 0.0f;

    for (int k0 = 0; k0 < HID; k0 += 64) {
#pragma unroll
        for (int t = tid; t < 1024; t += 256) {
            int r = t >> 4, c = (t & 15) * 4;
            int gr = rowBase + r;
            float4 v = make_float4(0.f, 0.f, 0.f, 0.f);
            if (gr < N)
                v = *(const float4*)(g_h1b + (size_t)gr * HID + k0 + c);
            *(float4*)&Xs[r][c] = v;
        }
#pragma unroll
        for (int t = tid; t < 1024; t += 256) {
            int r = t >> 4, c = (t & 15) * 4;
            *(float4*)&Ws[r][c] = *(const float4*)(W2 + (size_t)(k0 + r) * COUT + c);
        }
        __syncthreads();

#pragma unroll 4
        for (int k = 0; k < 64; k++) {
            float a[4];
#pragma unroll
            for (int i = 0; i < 4; i++) a[i] = Xs[ty * 4 + i][k];
            float4 b = *(float4*)&Ws[k][tx * 4];
#pragma unroll
            for (int i = 0; i < 4; i++) {
                acc[i][0] = fmaf(a[i], b.x, acc[i][0]);
                acc[i][1] = fmaf(a[i], b.y, acc[i][1]);
                acc[i][2] = fmaf(a[i], b.z, acc[i][2]);
                acc[i][3] = fmaf(a[i], b.w, acc[i][3]);
            }
        }
        __syncthreads();
    }

#pragma unroll
    for (int i = 0; i < 4; i++) {
        int gr = rowBase + ty * 4 + i;
        if (gr < N) {
            float4 o = make_float4(acc[i][0], acc[i][1], acc[i][2], acc[i][3]);
            *(float4*)(g_h2 + (size_t)gr * COUT + tx * 4) = o;
        }
    }
}

// ---------------------------------------------------------------------------
// Layer-1 aggregation (CSR, zero atomics) + bias + relu + embedding.
// One warp per dst node; each lane owns one float4 (128 cols / 32 lanes).
// h1b[d] = relu( dinv[d] * Σ_e h1[src_e]*dinv[src_e] + dinv[d]^2 * h1[d] + b1 )
// ---------------------------------------------------------------------------
__global__ void agg1_csr_kernel(const float* __restrict__ b1,
                                float* __restrict__ emb, int N) {
    int gid = blockIdx.x * blockDim.x + threadIdx.x;
    int d = gid >> 5;
    int lane = gid & 31;
    if (d >= N) return;

    int beg = g_off[d];
    int end = beg + g_cnt[d];

    float4 acc = make_float4(0.f, 0.f, 0.f, 0.f);
    // Software pipeline: prefetch next edge's (src, w) while gathering current.
    int s = 0; float w = 0.f;
    if (beg < end) { s = g_eidx[beg]; w = g_ew[beg]; }
    for (int j = beg; j < end; j++) {
        int s2 = 0; float w2 = 0.f;
        if (j + 1 < end) { s2 = g_eidx[j + 1]; w2 = g_ew[j + 1]; }
        float4 v = g_h1_4[(size_t)s * 32 + lane];
        acc.x = fmaf(v.x, w, acc.x);
        acc.y = fmaf(v.y, w, acc.y);
        acc.z = fmaf(v.z, w, acc.z);
        acc.w = fmaf(v.w, w, acc.w);
        s = s2; w = w2;
    }

    float dd = g_dinv[d];
    float dd2 = dd * dd;
    float4 hd = g_h1_4[(size_t)d * 32 + lane];
    float4 b = *(const float4*)(b1 + lane * 4);
    float4 r;
    r.x = fmaxf(fmaf(acc.x, dd, fmaf(hd.x, dd2, b.x)), 0.f);
    r.y = fmaxf(fmaf(acc.y, dd, fmaf(hd.y, dd2, b.y)), 0.f);
    r.z = fmaxf(fmaf(acc.z, dd, fmaf(hd.z, dd2, b.z)), 0.f);
    r.w = fmaxf(fmaf(acc.w, dd, fmaf(hd.w, dd2, b.w)), 0.f);
    g_h1b_4[(size_t)d * 32 + lane] = r;
    if (emb) ((float4*)emb)[(size_t)d * 32 + lane] = r;
}

// ---------------------------------------------------------------------------
// Layer-2 aggregation (CSR) + bias + fused warp log_softmax.
// One warp per dst node; each lane owns float2 (64 cols / 32 lanes).
// ---------------------------------------------------------------------------
__global__ void agg2_csr_kernel(const float* __restrict__ b2,
                                float* __restrict__ out, int N) {
    int gid = blockIdx.x * blockDim.x + threadIdx.x;
    int d = gid >> 5;
    int lane = gid & 31;
    if (d >= N) return;

    int beg = g_off[d];
    int end = beg + g_cnt[d];

    float2 acc = make_float2(0.f, 0.f);
    int s = 0; float w = 0.f;
    if (beg < end) { s = g_eidx[beg]; w = g_ew[beg]; }
    for (int j = beg; j < end; j++) {
        int s2 = 0; float w2 = 0.f;
        if (j + 1 < end) { s2 = g_eidx[j + 1]; w2 = g_ew[j + 1]; }
        float2 v = *(const float2*)(g_h2 + (size_t)s * COUT + lane * 2);
        acc.x = fmaf(v.x, w, acc.x);
        acc.y = fmaf(v.y, w, acc.y);
        s = s2; w = w2;
    }

    float dd = g_dinv[d];
    float dd2 = dd * dd;
    float2 hd = *(const float2*)(g_h2 + (size_t)d * COUT + lane * 2);
    float2 bb = *(const float2*)(b2 + lane * 2);
    float2 o;
    o.x = fmaf(acc.x, dd, fmaf(hd.x, dd2, bb.x));
    o.y = fmaf(acc.y, dd, fmaf(hd.y, dd2, bb.y));

    // Warp log_softmax over the 64 values.
    float m = fmaxf(o.x, o.y);
#pragma unroll
    for (int off = 16; off > 0; off >>= 1)
        m = fmaxf(m, __shfl_xor_sync(0xFFFFFFFFu, m, off));
    float sum = expf(o.x - m) + expf(o.y - m);
#pragma unroll
    for (int off = 16; off > 0; off >>= 1)
        sum += __shfl_xor_sync(0xFFFFFFFFu, sum, off);
    float l = logf(sum) + m;
    float2 r;
    r.x = o.x - l;
    r.y = o.y - l;
    *(float2*)(out + (size_t)d * COUT + lane * 2) = r;
}

// ---------------------------------------------------------------------------
extern "C" void kernel_launch(void* const* d_in, const int* in_sizes, int n_in,
                              void* d_out, int out_size) {
    const float* x  = (const float*)d_in[0];
    const float* W1 = (const float*)d_in[1];
    const float* b1 = (const float*)d_in[2];
    const float* W2 = (const float*)d_in[3];
    const float* b2 = (const float*)d_in[4];
    const void*  ei = d_in[5];

    const int H   = in_sizes[2];                 // 128
    const int Fin = in_sizes[1] / H;             // 96
    const int C   = in_sizes[4];                 // 64
    const int N   = in_sizes[0] / Fin;           // 100000
    const int E   = in_sizes[5] / 2;             // 800000

    float* out = (float*)d_out;
    float* emb = ((long long)out_size >= (long long)N * (C + H))
                     ? out + (size_t)N * C
                     : nullptr;

    const int T = 256;
    const int nblk = (N + 255) / 256;

    // Edge-index dtype detect + convert + in-degree count
    idx_reset_kernel<<<1, 1>>>();
    cnt_zero_kernel<<<(N + T - 1) / T, T>>>(N);
    idx_detect_kernel<<<256, 256>>>((const unsigned*)ei, E);
    idx_convert_count_kernel<<<(E + T - 1) / T, T>>>(ei, E);

    // CSR build: scan degrees, init dinv/cursors, scatter edges
    scanA_kernel<<<nblk, 256>>>(N);
    scanB_kernel<<<1, 512>>>(nblk);
    scanC_kernel<<<(N + T - 1) / T, T>>>(N);
    scatter_kernel<<<(E + T - 1) / T, T>>>(E);

    // Layer 1
    gemm1_kernel<<<(N + 63) / 64, 256>>>(x, W1, N);
    agg1_csr_kernel<<<(int)(((long long)N * 32 + T - 1) / T), T>>>(b1, emb, N);

    // Layer 2 (log_softmax fused into aggregation)
    gemm2_kernel<<<(N + 63) / 64, 256>>>(W2, N);
    agg2_csr_kernel<<<(int)(((long long)N * 32 + T - 1) / T), T>>>(b2, out, N);
}

// round 8
// speedup vs baseline: 2.7443x; 1.5977x over previous
#include <cuda_runtime.h>
#include <math.h>
#include <stdint.h>

// Problem shape (fixed by the dataset): N=100000, E=800000, F_IN=96, H=128, C=64.
#define MAXN 100000
#define MAXE 800000
#define FIN 96
#define HID 128
#define COUT 64
#define NBLK ((MAXN + 255) / 256)

// Scratch (static __device__ — no allocations allowed in kernel_launch).
__device__ float4 g_dinv4[(MAXN + 3) / 4];            // d^{-1/2}
__device__ float4 g_h1_4[(size_t)MAXN * HID / 4];     // x@W1
__device__ float4 g_h1b_4[(size_t)MAXN * HID / 4];    // relu(agg1+b1)
__device__ float4 g_h2_4[(size_t)MAXN * COUT / 4];    // h1b@W2
__device__ int    g_src[MAXE];
__device__ int    g_dst[MAXE];
__device__ int    g_cnt[MAXN];                        // in-degree (no self loop)
__device__ int    g_off[MAXN];                        // CSR row offsets
__device__ int    g_cur[MAXN];                        // scatter cursors
__device__ int    g_bsum[NBLK];
__device__ int    g_bbase[NBLK];
__device__ int    g_eidx[MAXE];                       // CSR: src per slot
__device__ float  g_ew[MAXE];                         // CSR: dinv[src] per slot
__device__ unsigned g_anyodd;

#define g_dinv ((float*)g_dinv4)
#define g_h1   ((float*)g_h1_4)
#define g_h1b  ((float*)g_h1b_4)
#define g_h2   ((float*)g_h2_4)

// ---------------------------------------------------------------------------
// TF32 helpers
// ---------------------------------------------------------------------------
__device__ __forceinline__ uint32_t f2tf32(float f) {
    uint32_t r;
    asm("cvt.rna.tf32.f32 %0, %1;" : "=r"(r) : "f"(f));
    return r;
}

__device__ __forceinline__ void mma_tf32(float* d, const uint32_t* a,
                                         uint32_t b0, uint32_t b1) {
    asm volatile(
        "mma.sync.aligned.m16n8k8.row.col.f32.tf32.tf32.f32 "
        "{%0,%1,%2,%3}, {%4,%5,%6,%7}, {%8,%9}, {%0,%1,%2,%3};"
        : "+f"(d[0]), "+f"(d[1]), "+f"(d[2]), "+f"(d[3])
        : "r"(a[0]), "r"(a[1]), "r"(a[2]), "r"(a[3]), "r"(b0), "r"(b1));
}

// ---------------------------------------------------------------------------
// edge_index dtype detection + conversion to int32.
// ---------------------------------------------------------------------------
__global__ void cnt_zero_reset_kernel(int N) {
    int i = blockIdx.x * blockDim.x + threadIdx.x;
    if (i < N) g_cnt[i] = 0;
    if (i == 0) g_anyodd = 0u;
}

__global__ void idx_detect_kernel(const unsigned* __restrict__ w, int E) {
    unsigned acc = 0u;
    for (int i = blockIdx.x * blockDim.x + threadIdx.x; i < E;
         i += gridDim.x * blockDim.x)
        acc |= w[2 * i + 1];
    for (int o = 16; o > 0; o >>= 1)
        acc |= __shfl_xor_sync(0xFFFFFFFFu, acc, o);
    if ((threadIdx.x & 31) == 0 && acc) atomicOr(&g_anyodd, acc);
}

__global__ void idx_convert_count_kernel(const void* __restrict__ ei, int E) {
    int e = blockIdx.x * blockDim.x + threadIdx.x;
    if (e >= E) return;
    int s, d;
    if (g_anyodd) {
        const int* p = (const int*)ei;
        s = p[e]; d = p[E + e];
    } else {
        const long long* p = (const long long*)ei;
        s = (int)p[e]; d = (int)p[E + e];
    }
    g_src[e] = s;
    g_dst[e] = d;
    atomicAdd(&g_cnt[d], 1);
}

// ---------------------------------------------------------------------------
// Exclusive scan of g_cnt into g_off (3 stages), then scatter to CSR.
// ---------------------------------------------------------------------------
__global__ void scanA_kernel(int N) {
    __shared__ int sm[256];
    int i = blockIdx.x * 256 + threadIdx.x;
    int v = (i < N) ? g_cnt[i] : 0;
    sm[threadIdx.x] = v;
    __syncthreads();
#pragma unroll
    for (int o = 1; o < 256; o <<= 1) {
        int t = (threadIdx.x >= o) ? sm[threadIdx.x - o] : 0;
        __syncthreads();
        sm[threadIdx.x] += t;
        __syncthreads();
    }
    if (i < N) g_off[i] = sm[threadIdx.x] - v;
    if (threadIdx.x == 255) g_bsum[blockIdx.x] = sm[255];
}

__global__ void scanB_kernel(int nblk) {
    __shared__ int sm[512];
    int i = threadIdx.x;
    int v = (i < nblk) ? g_bsum[i] : 0;
    sm[i] = v;
    __syncthreads();
#pragma unroll
    for (int o = 1; o < 512; o <<= 1) {
        int t = (i >= o) ? sm[i - o] : 0;
        __syncthreads();
        sm[i] += t;
        __syncthreads();
    }
    if (i < nblk) g_bbase[i] = sm[i] - v;
}

__global__ void scanC_kernel(int N) {
    int i = blockIdx.x * blockDim.x + threadIdx.x;
    if (i >= N) return;
    g_off[i] += g_bbase[i >> 8];
    g_cur[i] = 0;
    g_dinv[i] = rsqrtf((float)(g_cnt[i] + 1));
}

__global__ void scatter_kernel(int E) {
    int e = blockIdx.x * blockDim.x + threadIdx.x;
    if (e >= E) return;
    int s = g_src[e], d = g_dst[e];
    int pos = g_off[d] + atomicAdd(&g_cur[d], 1);
    g_eidx[pos] = s;
    g_ew[pos] = g_dinv[s];
}

// ---------------------------------------------------------------------------
// GEMM1 (TF32 tensor cores): g_h1[N,128] = x[N,96] @ W1[96,128]
// Block: 128 rows x 128 cols, 8 warps (4x2), warp = 32 rows x 64 cols.
// K chunks of 32; per k8 step: m16n8k8 MMA.
// ---------------------------------------------------------------------------
__global__ void gemm1_tc_kernel(const float* __restrict__ x,
                                const float* __restrict__ W1, int N) {
    __shared__ __align__(16) uint32_t Xs[128][36];   // pad 36: conflict-free frags
    __shared__ __align__(16) uint32_t Ws[32][132];
    const int tid = threadIdx.x;
    const int wid = tid >> 5;
    const int lane = tid & 31;
    const int gidl = lane >> 2;        // 0..7
    const int tig = lane & 3;          // 0..3
    const int warp_m = (wid >> 1) * 32;
    const int warp_n = (wid & 1) * 64;
    const int rowBase = blockIdx.x * 128;

    float acc[2][8][4];
#pragma unroll
    for (int mt = 0; mt < 2; mt++)
#pragma unroll
        for (int nt = 0; nt < 8; nt++)
#pragma unroll
            for (int i = 0; i < 4; i++) acc[mt][nt][i] = 0.0f;

    for (int k0 = 0; k0 < FIN; k0 += 32) {
        // Xs: 128x32 floats -> tf32 (1024 float4 loads)
#pragma unroll
        for (int t = tid; t < 1024; t += 256) {
            int r = t >> 3, c = (t & 7) * 4;
            int gr = rowBase + r;
            float4 v = make_float4(0.f, 0.f, 0.f, 0.f);
            if (gr < N) v = *(const float4*)(x + (size_t)gr * FIN + k0 + c);
            Xs[r][c + 0] = f2tf32(v.x);
            Xs[r][c + 1] = f2tf32(v.y);
            Xs[r][c + 2] = f2tf32(v.z);
            Xs[r][c + 3] = f2tf32(v.w);
        }
        // Ws: 32x128 floats -> tf32
#pragma unroll
        for (int t = tid; t < 1024; t += 256) {
            int r = t >> 5, c = (t & 31) * 4;
            float4 v = *(const float4*)(W1 + (size_t)(k0 + r) * HID + c);
            Ws[r][c + 0] = f2tf32(v.x);
            Ws[r][c + 1] = f2tf32(v.y);
            Ws[r][c + 2] = f2tf32(v.z);
            Ws[r][c + 3] = f2tf32(v.w);
        }
        __syncthreads();

#pragma unroll
        for (int kk = 0; kk < 4; kk++) {
            int k8 = kk * 8;
            uint32_t a[2][4];
#pragma unroll
            for (int mt = 0; mt < 2; mt++) {
                int mb = warp_m + mt * 16;
                a[mt][0] = Xs[mb + gidl][k8 + tig];
                a[mt][1] = Xs[mb + gidl + 8][k8 + tig];
                a[mt][2] = Xs[mb + gidl][k8 + tig + 4];
                a[mt][3] = Xs[mb + gidl + 8][k8 + tig + 4];
            }
#pragma unroll
            for (int nt = 0; nt < 8; nt++) {
                int nb = warp_n + nt * 8;
                uint32_t b0 = Ws[k8 + tig][nb + gidl];
                uint32_t b1 = Ws[k8 + tig + 4][nb + gidl];
                mma_tf32(acc[0][nt], a[0], b0, b1);
                mma_tf32(acc[1][nt], a[1], b0, b1);
            }
        }
        __syncthreads();
    }

#pragma unroll
    for (int mt = 0; mt < 2; mt++) {
#pragma unroll
        for (int nt = 0; nt < 8; nt++) {
            int col = warp_n + nt * 8 + 2 * tig;
            int r0 = rowBase + warp_m + mt * 16 + gidl;
            if (r0 < N)
                *(float2*)(g_h1 + (size_t)r0 * HID + col) =
                    make_float2(acc[mt][nt][0], acc[mt][nt][1]);
            if (r0 + 8 < N)
                *(float2*)(g_h1 + (size_t)(r0 + 8) * HID + col) =
                    make_float2(acc[mt][nt][2], acc[mt][nt][3]);
        }
    }
}

// ---------------------------------------------------------------------------
// GEMM2 (TF32 tensor cores): g_h2[N,64] = g_h1b[N,128] @ W2[128,64]
// Block: 128 rows x 64 cols, 8 warps; warp = 16 rows x 64 cols.
// ---------------------------------------------------------------------------
__global__ void gemm2_tc_kernel(const float* __restrict__ W2, int N) {
    __shared__ __align__(16) uint32_t Xs[128][36];
    __shared__ __align__(16) uint32_t Ws[32][68];
    const int tid = threadIdx.x;
    const int wid = tid >> 5;
    const int lane = tid & 31;
    const int gidl = lane >> 2;
    const int tig = lane & 3;
    const int warp_m = wid * 16;
    const int rowBase = blockIdx.x * 128;

    float acc[8][4];
#pragma unroll
    for (int nt = 0; nt < 8; nt++)
#pragma unroll
        for (int i = 0; i < 4; i++) acc[nt][i] = 0.0f;

    for (int k0 = 0; k0 < HID; k0 += 32) {
#pragma unroll
        for (int t = tid; t < 1024; t += 256) {
            int r = t >> 3, c = (t & 7) * 4;
            int gr = rowBase + r;
            float4 v = make_float4(0.f, 0.f, 0.f, 0.f);
            if (gr < N) v = *(const float4*)(g_h1b + (size_t)gr * HID + k0 + c);
            Xs[r][c + 0] = f2tf32(v.x);
            Xs[r][c + 1] = f2tf32(v.y);
            Xs[r][c + 2] = f2tf32(v.z);
            Xs[r][c + 3] = f2tf32(v.w);
        }
#pragma unroll
        for (int t = tid; t < 512; t += 256) {
            int r = t >> 4, c = (t & 15) * 4;
            float4 v = *(const float4*)(W2 + (size_t)(k0 + r) * COUT + c);
            Ws[r][c + 0] = f2tf32(v.x);
            Ws[r][c + 1] = f2tf32(v.y);
            Ws[r][c + 2] = f2tf32(v.z);
            Ws[r][c + 3] = f2tf32(v.w);
        }
        __syncthreads();

#pragma unroll
        for (int kk = 0; kk < 4; kk++) {
            int k8 = kk * 8;
            uint32_t a[4];
            a[0] = Xs[warp_m + gidl][k8 + tig];
            a[1] = Xs[warp_m + gidl + 8][k8 + tig];
            a[2] = Xs[warp_m + gidl][k8 + tig + 4];
            a[3] = Xs[warp_m + gidl + 8][k8 + tig + 4];
#pragma unroll
            for (int nt = 0; nt < 8; nt++) {
                int nb = nt * 8;
                uint32_t b0 = Ws[k8 + tig][nb + gidl];
                uint32_t b1 = Ws[k8 + tig + 4][nb + gidl];
                mma_tf32(acc[nt], a, b0, b1);
            }
        }
        __syncthreads();
    }

#pragma unroll
    for (int nt = 0; nt < 8; nt++) {
        int col = nt * 8 + 2 * tig;
        int r0 = rowBase + warp_m + gidl;
        if (r0 < N)
            *(float2*)(g_h2 + (size_t)r0 * COUT + col) =
                make_float2(acc[nt][0], acc[nt][1]);
        if (r0 + 8 < N)
            *(float2*)(g_h2 + (size_t)(r0 + 8) * COUT + col) =
                make_float2(acc[nt][2], acc[nt][3]);
    }
}

// ---------------------------------------------------------------------------
// Layer-1 aggregation (CSR, zero atomics) + bias + relu + embedding.
// One warp per dst; lane owns one float4; edge loop unrolled x2 for MLP.
// ---------------------------------------------------------------------------
__global__ void agg1_csr_kernel(const float* __restrict__ b1,
                                float* __restrict__ emb, int N) {
    int gid = blockIdx.x * blockDim.x + threadIdx.x;
    int d = gid >> 5;
    int lane = gid & 31;
    if (d >= N) return;

    int beg = g_off[d];
    int end = beg + g_cnt[d];

    float4 acc0 = make_float4(0.f, 0.f, 0.f, 0.f);
    float4 acc1 = make_float4(0.f, 0.f, 0.f, 0.f);
    int j = beg;
    for (; j + 1 < end; j += 2) {
        int s0 = g_eidx[j], s1 = g_eidx[j + 1];
        float w0 = g_ew[j], w1 = g_ew[j + 1];
        float4 v0 = g_h1_4[(size_t)s0 * 32 + lane];
        float4 v1 = g_h1_4[(size_t)s1 * 32 + lane];
        acc0.x = fmaf(v0.x, w0, acc0.x);
        acc0.y = fmaf(v0.y, w0, acc0.y);
        acc0.z = fmaf(v0.z, w0, acc0.z);
        acc0.w = fmaf(v0.w, w0, acc0.w);
        acc1.x = fmaf(v1.x, w1, acc1.x);
        acc1.y = fmaf(v1.y, w1, acc1.y);
        acc1.z = fmaf(v1.z, w1, acc1.z);
        acc1.w = fmaf(v1.w, w1, acc1.w);
    }
    if (j < end) {
        int s0 = g_eidx[j];
        float w0 = g_ew[j];
        float4 v0 = g_h1_4[(size_t)s0 * 32 + lane];
        acc0.x = fmaf(v0.x, w0, acc0.x);
        acc0.y = fmaf(v0.y, w0, acc0.y);
        acc0.z = fmaf(v0.z, w0, acc0.z);
        acc0.w = fmaf(v0.w, w0, acc0.w);
    }
    acc0.x += acc1.x; acc0.y += acc1.y; acc0.z += acc1.z; acc0.w += acc1.w;

    float dd = g_dinv[d];
    float dd2 = dd * dd;
    float4 hd = g_h1_4[(size_t)d * 32 + lane];
    float4 b = *(const float4*)(b1 + lane * 4);
    float4 r;
    r.x = fmaxf(fmaf(acc0.x, dd, fmaf(hd.x, dd2, b.x)), 0.f);
    r.y = fmaxf(fmaf(acc0.y, dd, fmaf(hd.y, dd2, b.y)), 0.f);
    r.z = fmaxf(fmaf(acc0.z, dd, fmaf(hd.z, dd2, b.z)), 0.f);
    r.w = fmaxf(fmaf(acc0.w, dd, fmaf(hd.w, dd2, b.w)), 0.f);
    g_h1b_4[(size_t)d * 32 + lane] = r;
    if (emb) ((float4*)emb)[(size_t)d * 32 + lane] = r;
}

// ---------------------------------------------------------------------------
// Layer-2 aggregation (CSR) + bias + fused warp log_softmax.
// ---------------------------------------------------------------------------
__global__ void agg2_csr_kernel(const float* __restrict__ b2,
                                float* __restrict__ out, int N) {
    int gid = blockIdx.x * blockDim.x + threadIdx.x;
    int d = gid >> 5;
    int lane = gid & 31;
    if (d >= N) return;

    int beg = g_off[d];
    int end = beg + g_cnt[d];

    float2 acc0 = make_float2(0.f, 0.f);
    float2 acc1 = make_float2(0.f, 0.f);
    int j = beg;
    for (; j + 1 < end; j += 2) {
        int s0 = g_eidx[j], s1 = g_eidx[j + 1];
        float w0 = g_ew[j], w1 = g_ew[j + 1];
        float2 v0 = *(const float2*)(g_h2 + (size_t)s0 * COUT + lane * 2);
        float2 v1 = *(const float2*)(g_h2 + (size_t)s1 * COUT + lane * 2);
        acc0.x = fmaf(v0.x, w0, acc0.x);
        acc0.y = fmaf(v0.y, w0, acc0.y);
        acc1.x = fmaf(v1.x, w1, acc1.x);
        acc1.y = fmaf(v1.y, w1, acc1.y);
    }
    if (j < end) {
        int s0 = g_eidx[j];
        float w0 = g_ew[j];
        float2 v0 = *(const float2*)(g_h2 + (size_t)s0 * COUT + lane * 2);
        acc0.x = fmaf(v0.x, w0, acc0.x);
        acc0.y = fmaf(v0.y, w0, acc0.y);
    }
    acc0.x += acc1.x; acc0.y += acc1.y;

    float dd = g_dinv[d];
    float dd2 = dd * dd;
    float2 hd = *(const float2*)(g_h2 + (size_t)d * COUT + lane * 2);
    float2 bb = *(const float2*)(b2 + lane * 2);
    float2 o;
    o.x = fmaf(acc0.x, dd, fmaf(hd.x, dd2, bb.x));
    o.y = fmaf(acc0.y, dd, fmaf(hd.y, dd2, bb.y));

    float m = fmaxf(o.x, o.y);
#pragma unroll
    for (int off = 16; off > 0; off >>= 1)
        m = fmaxf(m, __shfl_xor_sync(0xFFFFFFFFu, m, off));
    float sum = expf(o.x - m) + expf(o.y - m);
#pragma unroll
    for (int off = 16; off > 0; off >>= 1)
        sum += __shfl_xor_sync(0xFFFFFFFFu, sum, off);
    float l = logf(sum) + m;
    *(float2*)(out + (size_t)d * COUT + lane * 2) =
        make_float2(o.x - l, o.y - l);
}

// ---------------------------------------------------------------------------
extern "C" void kernel_launch(void* const* d_in, const int* in_sizes, int n_in,
                              void* d_out, int out_size) {
    const float* x  = (const float*)d_in[0];
    const float* W1 = (const float*)d_in[1];
    const float* b1 = (const float*)d_in[2];
    const float* W2 = (const float*)d_in[3];
    const float* b2 = (const float*)d_in[4];
    const void*  ei = d_in[5];

    const int H   = in_sizes[2];                 // 128
    const int Fin = in_sizes[1] / H;             // 96
    const int C   = in_sizes[4];                 // 64
    const int N   = in_sizes[0] / Fin;           // 100000
    const int E   = in_sizes[5] / 2;             // 800000

    float* out = (float*)d_out;
    float* emb = ((long long)out_size >= (long long)N * (C + H))
                     ? out + (size_t)N * C
                     : nullptr;

    const int T = 256;
    const int nblk = (N + 255) / 256;

    // Edge-index dtype detect + convert + in-degree count
    cnt_zero_reset_kernel<<<(N + T - 1) / T, T>>>(N);
    idx_detect_kernel<<<256, 256>>>((const unsigned*)ei, E);
    idx_convert_count_kernel<<<(E + T - 1) / T, T>>>(ei, E);

    // CSR build
    scanA_kernel<<<nblk, 256>>>(N);
    scanB_kernel<<<1, 512>>>(nblk);
    scanC_kernel<<<(N + T - 1) / T, T>>>(N);
    scatter_kernel<<<(E + T - 1) / T, T>>>(E);

    // Layer 1
    gemm1_tc_kernel<<<(N + 127) / 128, 256>>>(x, W1, N);
    agg1_csr_kernel<<<(int)(((long long)N * 32 + T - 1) / T), T>>>(b1, emb, N);

    // Layer 2 (log_softmax fused into aggregation)
    gemm2_tc_kernel<<<(N + 127) / 128, 256>>>(W2, N);
    agg2_csr_kernel<<<(int)(((long long)N * 32 + T - 1) / T), T>>>(b2, out, N);
}

// round 9
// speedup vs baseline: 2.7989x; 1.0199x over previous
#include <cuda_runtime.h>
#include <math.h>
#include <stdint.h>

// Problem shape (fixed by the dataset): N=100000, E=800000, F_IN=96, H=128, C=64.
#define MAXN 100000
#define MAXE 800000
#define FIN 96
#define HID 128
#define COUT 64
#define NBLK ((MAXN + 255) / 256)

// Scratch (static __device__ — no allocations allowed in kernel_launch).
__device__ float4 g_dinv4[(MAXN + 3) / 4];            // d^{-1/2}
__device__ float4 g_aggx_4[(size_t)MAXN * FIN / 4];   // Â·x  (96-wide)
__device__ float4 g_h1b_4[(size_t)MAXN * HID / 4];    // relu(aggx@W1+b1)
__device__ float4 g_h2_4[(size_t)MAXN * COUT / 4];    // h1b@W2
__device__ int    g_src[MAXE];
__device__ int    g_dst[MAXE];
__device__ int    g_cnt[MAXN];                        // in-degree (no self loop)
__device__ int    g_off[MAXN];                        // CSR row offsets
__device__ int    g_cur[MAXN];                        // scatter cursors
__device__ int    g_bsum[NBLK];
__device__ int    g_bbase[NBLK];
__device__ int    g_eidx[MAXE];                       // CSR: src per slot
__device__ float  g_ew[MAXE];                         // CSR: dinv[src] per slot
__device__ unsigned g_anyodd;

#define g_dinv ((float*)g_dinv4)
#define g_aggx ((float*)g_aggx_4)
#define g_h1b  ((float*)g_h1b_4)
#define g_h2   ((float*)g_h2_4)

// ---------------------------------------------------------------------------
// TF32 helpers
// ---------------------------------------------------------------------------
__device__ __forceinline__ uint32_t f2tf32(float f) {
    uint32_t r;
    asm("cvt.rna.tf32.f32 %0, %1;" : "=r"(r) : "f"(f));
    return r;
}

__device__ __forceinline__ void mma_tf32(float* d, const uint32_t* a,
                                         uint32_t b0, uint32_t b1) {
    asm volatile(
        "mma.sync.aligned.m16n8k8.row.col.f32.tf32.tf32.f32 "
        "{%0,%1,%2,%3}, {%4,%5,%6,%7}, {%8,%9}, {%0,%1,%2,%3};"
        : "+f"(d[0]), "+f"(d[1]), "+f"(d[2]), "+f"(d[3])
        : "r"(a[0]), "r"(a[1]), "r"(a[2]), "r"(a[3]), "r"(b0), "r"(b1));
}

// ---------------------------------------------------------------------------
// edge_index dtype detection + conversion to int32.
// ---------------------------------------------------------------------------
__global__ void cnt_zero_reset_kernel(int N) {
    int i = blockIdx.x * blockDim.x + threadIdx.x;
    if (i < N) g_cnt[i] = 0;
    if (i == 0) g_anyodd = 0u;
}

// Probe only the first few thousand odd words: enough to distinguish int32
// (odd words = real src ids, random in [0,N)) from int64 (odd words all 0).
__global__ void idx_detect_kernel(const unsigned* __restrict__ w, int E) {
    int limit = (E < 4096) ? E : 4096;
    unsigned acc = 0u;
    for (int i = threadIdx.x; i < limit; i += blockDim.x)
        acc |= w[2 * i + 1];
    for (int o = 16; o > 0; o >>= 1)
        acc |= __shfl_xor_sync(0xFFFFFFFFu, acc, o);
    if ((threadIdx.x & 31) == 0 && acc) atomicOr(&g_anyodd, acc);
}

__global__ void idx_convert_count_kernel(const void* __restrict__ ei, int E) {
    int e = blockIdx.x * blockDim.x + threadIdx.x;
    if (e >= E) return;
    int s, d;
    if (g_anyodd) {
        const int* p = (const int*)ei;
        s = p[e]; d = p[E + e];
    } else {
        const long long* p = (const long long*)ei;
        s = (int)p[e]; d = (int)p[E + e];
    }
    g_src[e] = s;
    g_dst[e] = d;
    atomicAdd(&g_cnt[d], 1);
}

// ---------------------------------------------------------------------------
// Exclusive scan of g_cnt into g_off (3 stages), then scatter to CSR.
// ---------------------------------------------------------------------------
__global__ void scanA_kernel(int N) {
    __shared__ int sm[256];
    int i = blockIdx.x * 256 + threadIdx.x;
    int v = (i < N) ? g_cnt[i] : 0;
    sm[threadIdx.x] = v;
    __syncthreads();
#pragma unroll
    for (int o = 1; o < 256; o <<= 1) {
        int t = (threadIdx.x >= o) ? sm[threadIdx.x - o] : 0;
        __syncthreads();
        sm[threadIdx.x] += t;
        __syncthreads();
    }
    if (i < N) g_off[i] = sm[threadIdx.x] - v;
    if (threadIdx.x == 255) g_bsum[blockIdx.x] = sm[255];
}

__global__ void scanB_kernel(int nblk) {
    __shared__ int sm[512];
    int i = threadIdx.x;
    int v = (i < nblk) ? g_bsum[i] : 0;
    sm[i] = v;
    __syncthreads();
#pragma unroll
    for (int o = 1; o < 512; o <<= 1) {
        int t = (i >= o) ? sm[i - o] : 0;
        __syncthreads();
        sm[i] += t;
        __syncthreads();
    }
    if (i < nblk) g_bbase[i] = sm[i] - v;
}

__global__ void scanC_kernel(int N) {
    int i = blockIdx.x * blockDim.x + threadIdx.x;
    if (i >= N) return;
    g_off[i] += g_bbase[i >> 8];
    g_cur[i] = 0;
    g_dinv[i] = rsqrtf((float)(g_cnt[i] + 1));
}

__global__ void scatter_kernel(int E) {
    int e = blockIdx.x * blockDim.x + threadIdx.x;
    if (e >= E) return;
    int s = g_src[e], d = g_dst[e];
    int pos = g_off[d] + atomicAdd(&g_cur[d], 1);
    g_eidx[pos] = s;
    g_ew[pos] = g_dinv[s];
}

// ---------------------------------------------------------------------------
// Input-space aggregation (CSR, zero atomics): aggx = Â·x  (96-wide).
// One warp per dst; lanes 0..23 each own one float4 (96 floats).
// aggx[d] = dinv[d]*Σ_e x[src_e]*dinv[src_e] + dinv[d]^2 * x[d]
// ---------------------------------------------------------------------------
__global__ void aggx_csr_kernel(const float* __restrict__ x, int N) {
    int gid = blockIdx.x * blockDim.x + threadIdx.x;
    int d = gid >> 5;
    int lane = gid & 31;
    if (d >= N || lane >= 24) return;

    int beg = g_off[d];
    int end = beg + g_cnt[d];

    float4 acc0 = make_float4(0.f, 0.f, 0.f, 0.f);
    float4 acc1 = make_float4(0.f, 0.f, 0.f, 0.f);
    int j = beg;
    for (; j + 1 < end; j += 2) {
        int s0 = g_eidx[j], s1 = g_eidx[j + 1];
        float w0 = g_ew[j], w1 = g_ew[j + 1];
        float4 v0 = *(const float4*)(x + (size_t)s0 * FIN + lane * 4);
        float4 v1 = *(const float4*)(x + (size_t)s1 * FIN + lane * 4);
        acc0.x = fmaf(v0.x, w0, acc0.x);
        acc0.y = fmaf(v0.y, w0, acc0.y);
        acc0.z = fmaf(v0.z, w0, acc0.z);
        acc0.w = fmaf(v0.w, w0, acc0.w);
        acc1.x = fmaf(v1.x, w1, acc1.x);
        acc1.y = fmaf(v1.y, w1, acc1.y);
        acc1.z = fmaf(v1.z, w1, acc1.z);
        acc1.w = fmaf(v1.w, w1, acc1.w);
    }
    if (j < end) {
        int s0 = g_eidx[j];
        float w0 = g_ew[j];
        float4 v0 = *(const float4*)(x + (size_t)s0 * FIN + lane * 4);
        acc0.x = fmaf(v0.x, w0, acc0.x);
        acc0.y = fmaf(v0.y, w0, acc0.y);
        acc0.z = fmaf(v0.z, w0, acc0.z);
        acc0.w = fmaf(v0.w, w0, acc0.w);
    }
    acc0.x += acc1.x; acc0.y += acc1.y; acc0.z += acc1.z; acc0.w += acc1.w;

    float dd = g_dinv[d];
    float dd2 = dd * dd;
    float4 xd = *(const float4*)(x + (size_t)d * FIN + lane * 4);
    float4 r;
    r.x = fmaf(acc0.x, dd, xd.x * dd2);
    r.y = fmaf(acc0.y, dd, xd.y * dd2);
    r.z = fmaf(acc0.z, dd, xd.z * dd2);
    r.w = fmaf(acc0.w, dd, xd.w * dd2);
    g_aggx_4[(size_t)d * 24 + lane] = r;
}

// ---------------------------------------------------------------------------
// GEMM1 (TF32): h1b[N,128] = relu(aggx[N,96] @ W1[96,128] + b1); also emb.
// Block: 128 rows x 128 cols, 8 warps (4x2), warp = 32 rows x 64 cols.
// ---------------------------------------------------------------------------
__global__ void gemm1_tc_kernel(const float* __restrict__ W1,
                                const float* __restrict__ b1,
                                float* __restrict__ emb, int N) {
    __shared__ __align__(16) uint32_t Xs[128][36];
    __shared__ __align__(16) uint32_t Ws[32][132];
    const int tid = threadIdx.x;
    const int wid = tid >> 5;
    const int lane = tid & 31;
    const int gidl = lane >> 2;
    const int tig = lane & 3;
    const int warp_m = (wid >> 1) * 32;
    const int warp_n = (wid & 1) * 64;
    const int rowBase = blockIdx.x * 128;

    float acc[2][8][4];
#pragma unroll
    for (int mt = 0; mt < 2; mt++)
#pragma unroll
        for (int nt = 0; nt < 8; nt++)
#pragma unroll
            for (int i = 0; i < 4; i++) acc[mt][nt][i] = 0.0f;

    for (int k0 = 0; k0 < FIN; k0 += 32) {
#pragma unroll
        for (int t = tid; t < 1024; t += 256) {
            int r = t >> 3, c = (t & 7) * 4;
            int gr = rowBase + r;
            float4 v = make_float4(0.f, 0.f, 0.f, 0.f);
            if (gr < N) v = *(const float4*)(g_aggx + (size_t)gr * FIN + k0 + c);
            Xs[r][c + 0] = f2tf32(v.x);
            Xs[r][c + 1] = f2tf32(v.y);
            Xs[r][c + 2] = f2tf32(v.z);
            Xs[r][c + 3] = f2tf32(v.w);
        }
#pragma unroll
        for (int t = tid; t < 1024; t += 256) {
            int r = t >> 5, c = (t & 31) * 4;
            float4 v = *(const float4*)(W1 + (size_t)(k0 + r) * HID + c);
            Ws[r][c + 0] = f2tf32(v.x);
            Ws[r][c + 1] = f2tf32(v.y);
            Ws[r][c + 2] = f2tf32(v.z);
            Ws[r][c + 3] = f2tf32(v.w);
        }
        __syncthreads();

#pragma unroll
        for (int kk = 0; kk < 4; kk++) {
            int k8 = kk * 8;
            uint32_t a[2][4];
#pragma unroll
            for (int mt = 0; mt < 2; mt++) {
                int mb = warp_m + mt * 16;
                a[mt][0] = Xs[mb + gidl][k8 + tig];
                a[mt][1] = Xs[mb + gidl + 8][k8 + tig];
                a[mt][2] = Xs[mb + gidl][k8 + tig + 4];
                a[mt][3] = Xs[mb + gidl + 8][k8 + tig + 4];
            }
#pragma unroll
            for (int nt = 0; nt < 8; nt++) {
                int nb = warp_n + nt * 8;
                uint32_t b0 = Ws[k8 + tig][nb + gidl];
                uint32_t b1v = Ws[k8 + tig + 4][nb + gidl];
                mma_tf32(acc[0][nt], a[0], b0, b1v);
                mma_tf32(acc[1][nt], a[1], b0, b1v);
            }
        }
        __syncthreads();
    }

    // Epilogue: +b1, relu, write h1b and embedding.
#pragma unroll
    for (int mt = 0; mt < 2; mt++) {
#pragma unroll
        for (int nt = 0; nt < 8; nt++) {
            int col = warp_n + nt * 8 + 2 * tig;
            float2 bb = *(const float2*)(b1 + col);
            int r0 = rowBase + warp_m + mt * 16 + gidl;
            if (r0 < N) {
                float2 v = make_float2(fmaxf(acc[mt][nt][0] + bb.x, 0.f),
                                       fmaxf(acc[mt][nt][1] + bb.y, 0.f));
                *(float2*)(g_h1b + (size_t)r0 * HID + col) = v;
                if (emb) *(float2*)(emb + (size_t)r0 * HID + col) = v;
            }
            if (r0 + 8 < N) {
                float2 v = make_float2(fmaxf(acc[mt][nt][2] + bb.x, 0.f),
                                       fmaxf(acc[mt][nt][3] + bb.y, 0.f));
                *(float2*)(g_h1b + (size_t)(r0 + 8) * HID + col) = v;
                if (emb) *(float2*)(emb + (size_t)(r0 + 8) * HID + col) = v;
            }
        }
    }
}

// ---------------------------------------------------------------------------
// GEMM2 (TF32): g_h2[N,64] = g_h1b[N,128] @ W2[128,64]
// ---------------------------------------------------------------------------
__global__ void gemm2_tc_kernel(const float* __restrict__ W2, int N) {
    __shared__ __align__(16) uint32_t Xs[128][36];
    __shared__ __align__(16) uint32_t Ws[32][68];
    const int tid = threadIdx.x;
    const int wid = tid >> 5;
    const int lane = tid & 31;
    const int gidl = lane >> 2;
    const int tig = lane & 3;
    const int warp_m = wid * 16;
    const int rowBase = blockIdx.x * 128;

    float acc[8][4];
#pragma unroll
    for (int nt = 0; nt < 8; nt++)
#pragma unroll
        for (int i = 0; i < 4; i++) acc[nt][i] = 0.0f;

    for (int k0 = 0; k0 < HID; k0 += 32) {
#pragma unroll
        for (int t = tid; t < 1024; t += 256) {
            int r = t >> 3, c = (t & 7) * 4;
            int gr = rowBase + r;
            float4 v = make_float4(0.f, 0.f, 0.f, 0.f);
            if (gr < N) v = *(const float4*)(g_h1b + (size_t)gr * HID + k0 + c);
            Xs[r][c + 0] = f2tf32(v.x);
            Xs[r][c + 1] = f2tf32(v.y);
            Xs[r][c + 2] = f2tf32(v.z);
            Xs[r][c + 3] = f2tf32(v.w);
        }
#pragma unroll
        for (int t = tid; t < 512; t += 256) {
            int r = t >> 4, c = (t & 15) * 4;
            float4 v = *(const float4*)(W2 + (size_t)(k0 + r) * COUT + c);
            Ws[r][c + 0] = f2tf32(v.x);
            Ws[r][c + 1] = f2tf32(v.y);
            Ws[r][c + 2] = f2tf32(v.z);
            Ws[r][c + 3] = f2tf32(v.w);
        }
        __syncthreads();

#pragma unroll
        for (int kk = 0; kk < 4; kk++) {
            int k8 = kk * 8;
            uint32_t a[4];
            a[0] = Xs[warp_m + gidl][k8 + tig];
            a[1] = Xs[warp_m + gidl + 8][k8 + tig];
            a[2] = Xs[warp_m + gidl][k8 + tig + 4];
            a[3] = Xs[warp_m + gidl + 8][k8 + tig + 4];
#pragma unroll
            for (int nt = 0; nt < 8; nt++) {
                int nb = nt * 8;
                uint32_t b0 = Ws[k8 + tig][nb + gidl];
                uint32_t b1 = Ws[k8 + tig + 4][nb + gidl];
                mma_tf32(acc[nt], a, b0, b1);
            }
        }
        __syncthreads();
    }

#pragma unroll
    for (int nt = 0; nt < 8; nt++) {
        int col = nt * 8 + 2 * tig;
        int r0 = rowBase + warp_m + gidl;
        if (r0 < N)
            *(float2*)(g_h2 + (size_t)r0 * COUT + col) =
                make_float2(acc[nt][0], acc[nt][1]);
        if (r0 + 8 < N)
            *(float2*)(g_h2 + (size_t)(r0 + 8) * COUT + col) =
                make_float2(acc[nt][2], acc[nt][3]);
    }
}

// ---------------------------------------------------------------------------
// Layer-2 aggregation (CSR) + bias + fused warp log_softmax.
// ---------------------------------------------------------------------------
__global__ void agg2_csr_kernel(const float* __restrict__ b2,
                                float* __restrict__ out, int N) {
    int gid = blockIdx.x * blockDim.x + threadIdx.x;
    int d = gid >> 5;
    int lane = gid & 31;
    if (d >= N) return;

    int beg = g_off[d];
    int end = beg + g_cnt[d];

    float2 acc0 = make_float2(0.f, 0.f);
    float2 acc1 = make_float2(0.f, 0.f);
    int j = beg;
    for (; j + 1 < end; j += 2) {
        int s0 = g_eidx[j], s1 = g_eidx[j + 1];
        float w0 = g_ew[j], w1 = g_ew[j + 1];
        float2 v0 = *(const float2*)(g_h2 + (size_t)s0 * COUT + lane * 2);
        float2 v1 = *(const float2*)(g_h2 + (size_t)s1 * COUT + lane * 2);
        acc0.x = fmaf(v0.x, w0, acc0.x);
        acc0.y = fmaf(v0.y, w0, acc0.y);
        acc1.x = fmaf(v1.x, w1, acc1.x);
        acc1.y = fmaf(v1.y, w1, acc1.y);
    }
    if (j < end) {
        int s0 = g_eidx[j];
        float w0 = g_ew[j];
        float2 v0 = *(const float2*)(g_h2 + (size_t)s0 * COUT + lane * 2);
        acc0.x = fmaf(v0.x, w0, acc0.x);
        acc0.y = fmaf(v0.y, w0, acc0.y);
    }
    acc0.x += acc1.x; acc0.y += acc1.y;

    float dd = g_dinv[d];
    float dd2 = dd * dd;
    float2 hd = *(const float2*)(g_h2 + (size_t)d * COUT + lane * 2);
    float2 bb = *(const float2*)(b2 + lane * 2);
    float2 o;
    o.x = fmaf(acc0.x, dd, fmaf(hd.x, dd2, bb.x));
    o.y = fmaf(acc0.y, dd, fmaf(hd.y, dd2, bb.y));

    float m = fmaxf(o.x, o.y);
#pragma unroll
    for (int off = 16; off > 0; off >>= 1)
        m = fmaxf(m, __shfl_xor_sync(0xFFFFFFFFu, m, off));
    float sum = expf(o.x - m) + expf(o.y - m);
#pragma unroll
    for (int off = 16; off > 0; off >>= 1)
        sum += __shfl_xor_sync(0xFFFFFFFFu, sum, off);
    float l = logf(sum) + m;
    *(float2*)(out + (size_t)d * COUT + lane * 2) =
        make_float2(o.x - l, o.y - l);
}

// ---------------------------------------------------------------------------
extern "C" void kernel_launch(void* const* d_in, const int* in_sizes, int n_in,
                              void* d_out, int out_size) {
    const float* x  = (const float*)d_in[0];
    const float* W1 = (const float*)d_in[1];
    const float* b1 = (const float*)d_in[2];
    const float* W2 = (const float*)d_in[3];
    const float* b2 = (const float*)d_in[4];
    const void*  ei = d_in[5];

    const int H   = in_sizes[2];                 // 128
    const int Fin = in_sizes[1] / H;             // 96
    const int C   = in_sizes[4];                 // 64
    const int N   = in_sizes[0] / Fin;           // 100000
    const int E   = in_sizes[5] / 2;             // 800000

    float* out = (float*)d_out;
    float* emb = ((long long)out_size >= (long long)N * (C + H))
                     ? out + (size_t)N * C
                     : nullptr;

    const int T = 256;
    const int nblk = (N + 255) / 256;

    // Edge-index dtype detect + convert + in-degree count
    cnt_zero_reset_kernel<<<(N + T - 1) / T, T>>>(N);
    idx_detect_kernel<<<1, 256>>>((const unsigned*)ei, E);
    idx_convert_count_kernel<<<(E + T - 1) / T, T>>>(ei, E);

    // CSR build
    scanA_kernel<<<nblk, 256>>>(N);
    scanB_kernel<<<1, 512>>>(nblk);
    scanC_kernel<<<(N + T - 1) / T, T>>>(N);
    scatter_kernel<<<(E + T - 1) / T, T>>>(E);

    // Layer 1: aggregate in input space (96-wide), then GEMM with fused
    // bias+relu+embedding epilogue.
    aggx_csr_kernel<<<(int)(((long long)N * 32 + T - 1) / T), T>>>(x, N);
    gemm1_tc_kernel<<<(N + 127) / 128, 256>>>(W1, b1, emb, N);

    // Layer 2: GEMM then aggregate in output space (64-wide) with fused
    // bias + log_softmax.
    gemm2_tc_kernel<<<(N + 127) / 128, 256>>>(W2, N);
    agg2_csr_kernel<<<(int)(((long long)N * 32 + T - 1) / T), T>>>(b2, out, N);
}